// round 5
// baseline (speedup 1.0000x reference)
#include <cuda_runtime.h>

// DirichletLoss: ball query (r=0.15, K=32 nearest within radius) + neighbor
// feature variance, mean over all B*N queries, *0.5.
//
// 2-kernel pipeline (graph-capturable, scratch in __device__ globals):
//   k_build : per-batch block — smem histogram, multi-warp shfl scan,
//             counting-sort into float4(x,y,z,f) cell-major; global offsets
//   k_main  : warp-per-query, two passes with per-row distance pruning:
//             A) key-only lane-distributed sorted top-32 distances,
//                rows skipped/clipped against the live cutoff
//             B) rescan with final cutoff, accumulate (f_i-f_j)^2
//             block partial -> last-block deterministic reduction -> out
//
// All candidate ranges are clamped so every loop terminates even if the
// offset table were corrupt (bugs become wrong answers, not hangs).

#define FULLMASK 0xFFFFFFFFu

constexpr int   B    = 8;
constexpr int   N    = 4096;
constexpr int   BN   = B * N;
constexpr int   GD   = 7;            // cells per axis (cell = r = 0.15)
constexpr int   NC   = GD * GD * GD; // 343 cells per batch
constexpr int   TOTC = B * NC;
constexpr int   NBLK = BN / 8;       // k_main blocks (8 warps each)
constexpr float CELL     = 0.15f;
constexpr float R2       = 0.15f * 0.15f;
constexpr float INV_CELL = 1.0f / 0.15f;
constexpr float BIGF     = 3.0e38f;

__device__ int      g_off[TOTC + 1];
__device__ float4   g_pts[BN];       // (x,y,z,f) sorted by global cell id
__device__ float    g_var[NBLK];     // per-block partial sums
__device__ unsigned g_done;          // last-block ticket

__device__ __forceinline__ int cell1(float x) {
    int c = (int)(x * INV_CELL);
    c = c < 0 ? 0 : c;
    return c > GD - 1 ? GD - 1 : c;
}

// min distance from coordinate v to cell slab [c*CELL, (c+1)*CELL)
__device__ __forceinline__ float slabdist(float v, int c) {
    return fmaxf(0.0f, fmaxf(c * CELL - v, v - (c + 1) * CELL));
}

// One block per batch: histogram -> multi-warp scan -> scatter.
__global__ void __launch_bounds__(1024) k_build(const float* __restrict__ pos,
                                                const float* __restrict__ f) {
    __shared__ int cnt[NC];
    __shared__ int sc [NC];          // inclusive per-warp scan
    __shared__ int wt [11], wb[11];  // warp totals / bases
    __shared__ int cur[NC];          // fill cursors (exclusive offsets)
    int b = blockIdx.x, t = threadIdx.x;
    int base = b * N;

    if (b == 0 && t == 0) g_done = 0;          // reset reduction ticket
    for (int i = t; i < NC; i += 1024) cnt[i] = 0;
    __syncthreads();

    float mx[4], my[4], mz[4], mf[4];
    int   mc[4];
    #pragma unroll
    for (int k = 0; k < 4; k++) {
        int gi = base + t + k * 1024;
        float x = pos[3 * gi], y = pos[3 * gi + 1], z = pos[3 * gi + 2];
        mx[k] = x; my[k] = y; mz[k] = z; mf[k] = f[gi];
        int c = (cell1(z) * GD + cell1(y)) * GD + cell1(x);
        mc[k] = c;
        atomicAdd(&cnt[c], 1);
    }
    __syncthreads();

    // 11 warps scan 32 cells each (352 >= NC=343).
    if (t < 352) {
        int w = t >> 5, l = t & 31;
        int x = (t < NC) ? cnt[t] : 0;
        int v = x;
        #pragma unroll
        for (int d = 1; d < 32; d <<= 1) {
            int u = __shfl_up_sync(FULLMASK, v, d);
            if (l >= d) v += u;
        }
        if (t < NC) sc[t] = v;                 // inclusive within warp
        if (l == 31) wt[w] = v;
    }
    __syncthreads();
    if (t < 32) {
        int v = (t < 11) ? wt[t] : 0;
        #pragma unroll
        for (int d = 1; d < 32; d <<= 1) {
            int u = __shfl_up_sync(FULLMASK, v, d);
            if (t >= d) v += u;
        }
        if (t < 11) wb[t] = v - wt[t];         // exclusive warp base
    }
    __syncthreads();
    if (t < NC) {
        int ex = sc[t] - cnt[t] + wb[t >> 5];  // exclusive offset
        cur[t] = ex;
        g_off[b * NC + t] = base + ex;
    }
    if (b == B - 1 && t == 0) g_off[TOTC] = BN;
    __syncthreads();

    #pragma unroll
    for (int k = 0; k < 4; k++) {
        int dst = base + atomicAdd(&cur[mc[k]], 1);
        if (dst >= 0 && dst < BN)
            g_pts[dst] = make_float4(mx[k], my[k], mz[k], mf[k]);
    }
}

// One warp per query; last block reduces.
__global__ void __launch_bounds__(256) k_main(float* __restrict__ out) {
    __shared__ float  swarp[8];
    __shared__ double sd[256];
    __shared__ bool   amLast;
    int lane = threadIdx.x & 31;
    int wid  = threadIdx.x >> 5;
    int q    = blockIdx.x * 8 + wid;

    float4 p = g_pts[q];
    int b   = q >> 12;                // sorted array stays batch-contiguous
    int bNC = b * NC;
    int cx = cell1(p.x), cy = cell1(p.y), cz = cell1(p.z);

    float kd = BIGF;                  // lane-sorted ascending distance keys
    float cutoff = BIGF;

    const int dzs[3] = {0, -1, 1};
    const int dys[3] = {0, -1, 1};

    // ---- Pass A: top-32 distance keys, rows pruned by live cutoff ----
    #pragma unroll
    for (int zi = 0; zi < 3; zi++) {
        int z = cz + dzs[zi];
        if (z < 0 || z >= GD) continue;
        float dzm = slabdist(p.z, z);
        #pragma unroll
        for (int yi = 0; yi < 3; yi++) {
            int y = cy + dys[yi];
            if (y < 0 || y >= GD) continue;
            float dym = slabdist(p.y, y);
            float rowmin2 = fmaf(dzm, dzm, dym * dym);
            float cutmin  = fminf(cutoff, R2);
            if (rowmin2 > cutmin) continue;           // row can't contribute
            float rx = sqrtf(cutmin - rowmin2) * 1.0001f + 1e-6f;
            int xl = cell1(p.x - rx), xh = cell1(p.x + rx);
            int rb = bNC + (z * GD + y) * GD;
            int s0 = g_off[rb + xl];
            int s1 = g_off[rb + xh + 1];              // contiguous cell row
            s0 = s0 < 0 ? 0 : s0;                     // termination guards
            s1 = s1 > BN ? BN : s1;
            for (int base0 = s0; base0 < s1; base0 += 32) {
                int j = base0 + lane;
                float d2 = BIGF;
                if (j < s1) {
                    float4 c = g_pts[j];
                    float dx = c.x - p.x, dy = c.y - p.y, dz = c.z - p.z;
                    d2 = fmaf(dx, dx, fmaf(dy, dy, dz * dz));
                }
                unsigned want =
                    __ballot_sync(FULLMASK, d2 <= R2 && d2 < cutoff);
                if (want) {
                    do {
                        int src = __ffs(want) - 1;
                        want &= want - 1;
                        float v  = __shfl_sync(FULLMASK, d2, src);
                        float pd = __shfl_up_sync(FULLMASK, kd, 1);
                        if (lane == 0) pd = -BIGF;
                        if (kd > v) kd = fmaxf(pd, v);   // sorted insert
                    } while (want);
                    cutoff = __shfl_sync(FULLMASK, kd, 31);
                }
            }
        }
    }

    // Final selection threshold: 32nd-smallest distance, capped at R2.
    float cutB = fminf(cutoff, R2);

    // ---- Pass B: rescan with final cutoff, accumulate variance ----
    float acc = 0.0f;
    #pragma unroll
    for (int zi = 0; zi < 3; zi++) {
        int z = cz + dzs[zi];
        if (z < 0 || z >= GD) continue;
        float dzm = slabdist(p.z, z);
        #pragma unroll
        for (int yi = 0; yi < 3; yi++) {
            int y = cy + dys[yi];
            if (y < 0 || y >= GD) continue;
            float dym = slabdist(p.y, y);
            float rowmin2 = fmaf(dzm, dzm, dym * dym);
            if (rowmin2 > cutB) continue;
            float rx = sqrtf(cutB - rowmin2) * 1.0001f + 1e-6f;
            int xl = cell1(p.x - rx), xh = cell1(p.x + rx);
            int rb = bNC + (z * GD + y) * GD;
            int s0 = g_off[rb + xl];
            int s1 = g_off[rb + xh + 1];
            s0 = s0 < 0 ? 0 : s0;
            s1 = s1 > BN ? BN : s1;
            for (int base0 = s0; base0 < s1; base0 += 32) {
                int j = base0 + lane;
                if (j < s1) {
                    float4 c = g_pts[j];
                    float dx = c.x - p.x, dy = c.y - p.y, dz = c.z - p.z;
                    float d2 = fmaf(dx, dx, fmaf(dy, dy, dz * dz));
                    if (d2 <= cutB) {
                        float df = p.w - c.w;
                        acc = fmaf(df, df, acc);
                    }
                }
            }
        }
    }

    #pragma unroll
    for (int o = 16; o; o >>= 1) acc += __shfl_xor_sync(FULLMASK, acc, o);
    if (lane == 0) swarp[wid] = acc;
    __syncthreads();
    if (threadIdx.x == 0) {
        float s = 0.0f;
        #pragma unroll
        for (int w = 0; w < 8; w++) s += swarp[w];
        g_var[blockIdx.x] = s;
    }

    // ---- last-block deterministic reduction ----
    __threadfence();
    if (threadIdx.x == 0)
        amLast = (atomicAdd(&g_done, 1u) == (unsigned)(NBLK - 1));
    __syncthreads();
    if (amLast) {
        double a = 0.0;
        for (int i = threadIdx.x; i < NBLK; i += 256) a += (double)g_var[i];
        sd[threadIdx.x] = a;
        __syncthreads();
        for (int d = 128; d; d >>= 1) {
            if (threadIdx.x < d) sd[threadIdx.x] += sd[threadIdx.x + d];
            __syncthreads();
        }
        if (threadIdx.x == 0) out[0] = (float)(0.5 * sd[0] / (double)BN);
    }
}

extern "C" void kernel_launch(void* const* d_in, const int* in_sizes, int n_in,
                              void* d_out, int out_size) {
    const float* pos = (const float*)d_in[0];
    const float* f   = (const float*)d_in[1];
    if (n_in >= 2 && in_sizes[0] == BN && in_sizes[1] == 3 * BN) {
        const float* tmp = pos; pos = f; f = tmp;   // defensive input order
    }
    float* out = (float*)d_out;

    k_build<<<B, 1024>>>(pos, f);
    k_main<<<NBLK, 256>>>(out);
}

// round 6
// speedup vs baseline: 1.4696x; 1.4696x over previous
#include <cuda_runtime.h>

// DirichletLoss: ball query (r=0.15, K=32 nearest within radius) + neighbor
// feature variance, mean over all B*N queries, *0.5.
//
// 2-kernel pipeline (graph-capturable, scratch in __device__ globals):
//   k_build : per-batch block — smem histogram, multi-warp shfl scan,
//             counting-sort into float4(x,y,z,f) cell-major; global offsets
//   k_main  : warp-per-query, SINGLE pass. Selection keys are packed
//             uint32 = (d2 float bits & ~0xFFF) | batch-local point index,
//             so the sorted top-32 list carries neighbor identity and the
//             epilogue gathers f_j directly — no second scan pass.
//             Block partial -> last-block deterministic reduction -> out.
//
// All candidate ranges are clamped so every loop terminates even if the
// offset table were corrupt (bugs become wrong answers, not hangs).

#define FULLMASK 0xFFFFFFFFu

constexpr int   B    = 8;
constexpr int   N    = 4096;
constexpr int   BN   = B * N;
constexpr int   GD   = 7;            // cells per axis (cell = r = 0.15)
constexpr int   NC   = GD * GD * GD; // 343 cells per batch
constexpr int   TOTC = B * NC;
constexpr int   NBLK = BN / 8;       // k_main blocks (8 warps each)
constexpr float R2       = 0.15f * 0.15f;
constexpr float INV_CELL = 1.0f / 0.15f;
constexpr float BIGF     = 3.0e38f;
constexpr unsigned SENT  = 0xFFFFFFFFu;   // > any real packed key

__device__ int      g_off[TOTC + 1];
__device__ float4   g_pts[BN];       // (x,y,z,f) sorted by global cell id
__device__ float    g_var[NBLK];     // per-block partial sums
__device__ unsigned g_done;          // last-block ticket

__device__ __forceinline__ int cell1(float x) {
    int c = (int)(x * INV_CELL);
    c = c < 0 ? 0 : c;
    return c > GD - 1 ? GD - 1 : c;
}

// One block per batch: histogram -> multi-warp scan -> scatter.
__global__ void __launch_bounds__(1024) k_build(const float* __restrict__ pos,
                                                const float* __restrict__ f) {
    __shared__ int cnt[NC];
    __shared__ int sc [NC];          // inclusive per-warp scan
    __shared__ int wt [11], wb[11];  // warp totals / bases
    __shared__ int cur[NC];          // fill cursors (exclusive offsets)
    int b = blockIdx.x, t = threadIdx.x;
    int base = b * N;

    if (b == 0 && t == 0) g_done = 0;          // reset reduction ticket
    for (int i = t; i < NC; i += 1024) cnt[i] = 0;
    __syncthreads();

    float mx[4], my[4], mz[4], mf[4];
    int   mc[4];
    #pragma unroll
    for (int k = 0; k < 4; k++) {
        int gi = base + t + k * 1024;
        float x = pos[3 * gi], y = pos[3 * gi + 1], z = pos[3 * gi + 2];
        mx[k] = x; my[k] = y; mz[k] = z; mf[k] = f[gi];
        int c = (cell1(z) * GD + cell1(y)) * GD + cell1(x);
        mc[k] = c;
        atomicAdd(&cnt[c], 1);
    }
    __syncthreads();

    // 11 warps scan 32 cells each (352 >= NC=343).
    if (t < 352) {
        int w = t >> 5, l = t & 31;
        int x = (t < NC) ? cnt[t] : 0;
        int v = x;
        #pragma unroll
        for (int d = 1; d < 32; d <<= 1) {
            int u = __shfl_up_sync(FULLMASK, v, d);
            if (l >= d) v += u;
        }
        if (t < NC) sc[t] = v;                 // inclusive within warp
        if (l == 31) wt[w] = v;
    }
    __syncthreads();
    if (t < 32) {
        int v = (t < 11) ? wt[t] : 0;
        #pragma unroll
        for (int d = 1; d < 32; d <<= 1) {
            int u = __shfl_up_sync(FULLMASK, v, d);
            if (t >= d) v += u;
        }
        if (t < 11) wb[t] = v - wt[t];         // exclusive warp base
    }
    __syncthreads();
    if (t < NC) {
        int ex = sc[t] - cnt[t] + wb[t >> 5];  // exclusive offset
        cur[t] = ex;
        g_off[b * NC + t] = base + ex;
    }
    if (b == B - 1 && t == 0) g_off[TOTC] = BN;
    __syncthreads();

    #pragma unroll
    for (int k = 0; k < 4; k++) {
        int dst = base + atomicAdd(&cur[mc[k]], 1);
        if (dst >= 0 && dst < BN)
            g_pts[dst] = make_float4(mx[k], my[k], mz[k], mf[k]);
    }
}

// One warp per query; single scan pass; last block reduces.
__global__ void __launch_bounds__(256) k_main(float* __restrict__ out) {
    __shared__ float  swarp[8];
    __shared__ double sd[256];
    __shared__ bool   amLast;
    int lane = threadIdx.x & 31;
    int wid  = threadIdx.x >> 5;
    int q    = blockIdx.x * 8 + wid;

    float4 p = g_pts[q];
    int b    = q >> 12;               // sorted array stays batch-contiguous
    int base = b * N;
    int bNC  = b * NC;
    int cx = cell1(p.x), cy = cell1(p.y), cz = cell1(p.z);
    int xlo = cx > 0 ? cx - 1 : 0, xhi = cx < GD - 1 ? cx + 1 : GD - 1;

    unsigned kk = SENT;               // lane-sorted ascending packed keys
    unsigned cutoffU = SENT;          // lane-31 key (32nd smallest)

    // Center row first so the cutoff tightens early.
    const int dzs[3] = {0, -1, 1};
    const int dys[3] = {0, -1, 1};
    #pragma unroll
    for (int zi = 0; zi < 3; zi++) {
        int z = cz + dzs[zi];
        if (z < 0 || z >= GD) continue;
        #pragma unroll
        for (int yi = 0; yi < 3; yi++) {
            int y = cy + dys[yi];
            if (y < 0 || y >= GD) continue;
            int rb = bNC + (z * GD + y) * GD;
            int s0 = g_off[rb + xlo];
            int s1 = g_off[rb + xhi + 1];         // contiguous 3-cell row
            s0 = s0 < 0 ? 0 : s0;                 // termination guards
            s1 = s1 > BN ? BN : s1;
            for (int base0 = s0; base0 < s1; base0 += 32) {
                int j = base0 + lane;
                float d2 = BIGF;
                unsigned pk = SENT;
                if (j < s1) {
                    float4 c = g_pts[j];
                    float dx = c.x - p.x, dy = c.y - p.y, dz = c.z - p.z;
                    d2 = fmaf(dx, dx, fmaf(dy, dy, dz * dz));
                    pk = (__float_as_uint(d2) & 0xFFFFF000u) |
                         (unsigned)(j - base);
                }
                unsigned want =
                    __ballot_sync(FULLMASK, d2 <= R2 && pk < cutoffU);
                if (want) {
                    do {
                        int src = __ffs(want) - 1;
                        want &= want - 1;
                        unsigned v  = __shfl_sync(FULLMASK, pk, src);
                        unsigned pd = __shfl_up_sync(FULLMASK, kk, 1);
                        if (lane == 0) pd = 0u;
                        if (kk > v) kk = pd > v ? pd : v;  // sorted insert
                    } while (want);
                    cutoffU = __shfl_sync(FULLMASK, kk, 31);
                }
            }
        }
    }

    // Epilogue: each lane holds one selected neighbor (or sentinel).
    float acc = 0.0f;
    if (kk != SENT) {
        int j = (int)(kk & 0xFFFu);
        float fj = g_pts[base + j].w;
        float df = p.w - fj;
        acc = df * df;
    }
    #pragma unroll
    for (int o = 16; o; o >>= 1) acc += __shfl_xor_sync(FULLMASK, acc, o);
    if (lane == 0) swarp[wid] = acc;
    __syncthreads();
    if (threadIdx.x == 0) {
        float s = 0.0f;
        #pragma unroll
        for (int w = 0; w < 8; w++) s += swarp[w];
        g_var[blockIdx.x] = s;
    }

    // ---- last-block deterministic reduction ----
    __threadfence();
    if (threadIdx.x == 0)
        amLast = (atomicAdd(&g_done, 1u) == (unsigned)(NBLK - 1));
    __syncthreads();
    if (amLast) {
        double a = 0.0;
        for (int i = threadIdx.x; i < NBLK; i += 256) a += (double)g_var[i];
        sd[threadIdx.x] = a;
        __syncthreads();
        for (int d = 128; d; d >>= 1) {
            if (threadIdx.x < d) sd[threadIdx.x] += sd[threadIdx.x + d];
            __syncthreads();
        }
        if (threadIdx.x == 0) out[0] = (float)(0.5 * sd[0] / (double)BN);
    }
}

extern "C" void kernel_launch(void* const* d_in, const int* in_sizes, int n_in,
                              void* d_out, int out_size) {
    const float* pos = (const float*)d_in[0];
    const float* f   = (const float*)d_in[1];
    if (n_in >= 2 && in_sizes[0] == BN && in_sizes[1] == 3 * BN) {
        const float* tmp = pos; pos = f; f = tmp;   // defensive input order
    }
    float* out = (float*)d_out;

    k_build<<<B, 1024>>>(pos, f);
    k_main<<<NBLK, 256>>>(out);
}